// round 11
// baseline (speedup 1.0000x reference)
#include <cuda_runtime.h>
#include <cstdint>

// x: [N=64, C=512, H=56, W=56] fp32. 2:4 structured sparsity along C:
// within each group of 4 channels (same n,h,w), zero the 2 smallest-|x|
// entries (ties: lower channel index dropped first, matching jax top_k).
//
// R11 = R7 (session best, 121.3us / DRAM 85.4%) with the last two
// unmeasured micro-cells:
//  - __ldcs loads x __stwt stores (the one untested cache-policy cross;
//    .wt stores never allocate, so L2 is a pure read buffer and .cs
//    keeps read-line occupancy minimal)
//  - dead bounds-check removed: TOTAL_T = 6,422,528 = 25088 x 256
//    exactly, so every thread is in range.
//
// Session evidence: floor = 121.3-122.0us across R1/R3/R4/R6/R7/R8/R9/R10
// (6.7-6.8 TB/s = 84-85% of spec, the B300 r+w streaming ceiling).
// R2 (MLP=8, occ 40%) and R5 (persistent grid-stride) regressed.

static constexpr int HW4     = (56 * 56) / 4;   // 784 float4 per channel plane
static constexpr int TOTAL_T = 64 * 128 * HW4;  // 6,422,528 = 25088 * 256
static_assert(TOTAL_T % 256 == 0, "grid divides exactly; no tail guard");

// keep element i iff at least 2 of the other 3 are "strictly smaller"
// under less(j,i) = (|a_j| < |a_i|) || (|a_j| == |a_i| && j < i),
// matching jax top_k(-|x|, 2) one-hot drop semantics exactly.
__device__ __forceinline__ void mask4(float& x0, float& x1, float& x2, float& x3) {
    float a0 = fabsf(x0), a1 = fabsf(x1), a2 = fabsf(x2), a3 = fabsf(x3);
    int r0 = 0, r1 = 0, r2 = 0, r3 = 0;
    if (a0 <= a1) r1++; else r0++;   // less(0,1)=a0<=a1 ; less(1,0)=a1<a0
    if (a0 <= a2) r2++; else r0++;
    if (a0 <= a3) r3++; else r0++;
    if (a1 <= a2) r2++; else r1++;
    if (a1 <= a3) r3++; else r1++;
    if (a2 <= a3) r3++; else r2++;
    x0 = (r0 >= 2) ? x0 : 0.0f;
    x1 = (r1 >= 2) ? x1 : 0.0f;
    x2 = (r2 >= 2) ? x2 : 0.0f;
    x3 = (r3 >= 2) ? x3 : 0.0f;
}

__global__ void __launch_bounds__(256, 8)
sparsity24_kernel(const float4* __restrict__ x4, float4* __restrict__ o4) {
    int t = blockIdx.x * 256 + threadIdx.x;   // always < TOTAL_T (exact grid)

    // decode: t -> (ng, hw4); constant divisor -> mul-shift in SASS
    int hw4 = t % HW4;
    int ng  = t / HW4;
    int base = ng * (4 * HW4) + hw4;   // max 25,690,112 < 2^31

    float4 v0 = __ldcs(&x4[base]);
    float4 v1 = __ldcs(&x4[base + HW4]);
    float4 v2 = __ldcs(&x4[base + 2 * HW4]);
    float4 v3 = __ldcs(&x4[base + 3 * HW4]);

    mask4(v0.x, v1.x, v2.x, v3.x);
    mask4(v0.y, v1.y, v2.y, v3.y);
    mask4(v0.z, v1.z, v2.z, v3.z);
    mask4(v0.w, v1.w, v2.w, v3.w);

    __stwt(&o4[base],           v0);
    __stwt(&o4[base + HW4],     v1);
    __stwt(&o4[base + 2 * HW4], v2);
    __stwt(&o4[base + 3 * HW4], v3);
}

extern "C" void kernel_launch(void* const* d_in, const int* in_sizes, int n_in,
                              void* d_out, int out_size) {
    const float4* x4 = (const float4*)d_in[0];
    float4* o4 = (float4*)d_out;
    sparsity24_kernel<<<TOTAL_T / 256, 256>>>(x4, o4);
}

// round 12
// speedup vs baseline: 1.0211x; 1.0211x over previous
#include <cuda_runtime.h>
#include <cstdint>

// x: [N=64, C=512, H=56, W=56] fp32. 2:4 structured sparsity along C:
// within each group of 4 channels (same n,h,w), zero the 2 smallest-|x|
// entries (ties: lower channel index dropped first, matching jax top_k).
//
// FINAL — byte-identical to R7, the measured session best:
//   121.3us bench / 113.4us ncu / DRAM 85.4% / 6.78 TB/s end-to-end
//   (84.7% of 8 TB/s spec = the B300 read+write streaming ceiling).
//
// Every design choice below was measured against alternatives over 11
// rounds on GB300 (sm_103a):
//  - one thread per (4-channel group x float4 hw column): 4 coalesced
//    float4 loads strided by the channel plane (per-thread MLP=4),
//    regs=32, occ ~80%. MLP=8/thread (regs 60, occ 40%) regressed 7%.
//  - fresh-CTA launch, block=256 (~21 waves). Persistent grid-stride
//    (1 wave) regressed 16% — the loop serializes load batches.
//    block=512 was neutral-worse.
//  - PLAIN loads: measured better than .cs (R3/R11) and equal to .cg
//    (R9). .cs loads raised L1 activity 22 points and cost 2.6us (R11).
//  - __stwt write-through stores: output never re-read; skipping L2
//    write-allocate was the only measurable cache-policy win
//    (DRAM 83.7 -> 85.4%).
//  - 32-bit index math (max float4 index 25,690,112 < 2^31); the
//    bounds guard stays — removing it let ptxas reschedule into a
//    worse instruction mix (R11).

static constexpr int HW4     = (56 * 56) / 4;   // 784 float4 per channel plane
static constexpr int TOTAL_T = 64 * 128 * HW4;  // 6,422,528 (fits int)

// keep element i iff at least 2 of the other 3 are "strictly smaller"
// under less(j,i) = (|a_j| < |a_i|) || (|a_j| == |a_i| && j < i),
// matching jax top_k(-|x|, 2) one-hot drop semantics exactly.
__device__ __forceinline__ void mask4(float& x0, float& x1, float& x2, float& x3) {
    float a0 = fabsf(x0), a1 = fabsf(x1), a2 = fabsf(x2), a3 = fabsf(x3);
    int r0 = 0, r1 = 0, r2 = 0, r3 = 0;
    if (a0 <= a1) r1++; else r0++;   // less(0,1)=a0<=a1 ; less(1,0)=a1<a0
    if (a0 <= a2) r2++; else r0++;
    if (a0 <= a3) r3++; else r0++;
    if (a1 <= a2) r2++; else r1++;
    if (a1 <= a3) r3++; else r1++;
    if (a2 <= a3) r3++; else r2++;
    x0 = (r0 >= 2) ? x0 : 0.0f;
    x1 = (r1 >= 2) ? x1 : 0.0f;
    x2 = (r2 >= 2) ? x2 : 0.0f;
    x3 = (r3 >= 2) ? x3 : 0.0f;
}

__global__ void __launch_bounds__(256, 8)
sparsity24_kernel(const float4* __restrict__ x4, float4* __restrict__ o4) {
    int t = blockIdx.x * 256 + threadIdx.x;
    if (t >= TOTAL_T) return;

    // decode: t -> (ng, hw4); constant divisor -> mul-shift in SASS
    int hw4 = t % HW4;
    int ng  = t / HW4;
    int base = ng * (4 * HW4) + hw4;   // max 25,690,112 < 2^31

    float4 v0 = x4[base];
    float4 v1 = x4[base + HW4];
    float4 v2 = x4[base + 2 * HW4];
    float4 v3 = x4[base + 3 * HW4];

    mask4(v0.x, v1.x, v2.x, v3.x);
    mask4(v0.y, v1.y, v2.y, v3.y);
    mask4(v0.z, v1.z, v2.z, v3.z);
    mask4(v0.w, v1.w, v2.w, v3.w);

    __stwt(&o4[base],           v0);
    __stwt(&o4[base + HW4],     v1);
    __stwt(&o4[base + 2 * HW4], v2);
    __stwt(&o4[base + 3 * HW4], v3);
}

extern "C" void kernel_launch(void* const* d_in, const int* in_sizes, int n_in,
                              void* d_out, int out_size) {
    const float4* x4 = (const float4*)d_in[0];
    float4* o4 = (float4*)d_out;
    int blocks = (TOTAL_T + 255) / 256;
    sparsity24_kernel<<<blocks, 256>>>(x4, o4);
}